// round 8
// baseline (speedup 1.0000x reference)
#include <cuda_runtime.h>
#include <cstdint>
#include <mma.h>
#include <math.h>

using namespace nvcuda;

#define D_MODEL 1024
#define N_HEADS 16
#define DK 64
#define BATCH 2
#define SEQ 2048
#define M_TOT (BATCH * SEQ)   // 4096
#define NX (M_TOT * D_MODEL)
#define NW (D_MODEL * D_MODEL)

__device__ float g_Q[BATCH * N_HEADS * SEQ * DK];   // [B,H,S,dk] tf32-rounded
__device__ float g_K[BATCH * N_HEADS * SEQ * DK];
__device__ float g_V[BATCH * N_HEADS * SEQ * DK];
__device__ float g_ctx[BATCH * SEQ * D_MODEL];      // [B,S,D]
__device__ float g_xr[NX];                          // tf32-rounded x
__device__ float g_Wr[4 * NW];                      // tf32-rounded Wq,Wk,Wv,Wo

__device__ __forceinline__ float rtf32(float a) {
    float r;
    asm("cvt.rna.tf32.f32 %0, %1;" : "=f"(r) : "f"(a));
    return r;
}

// fast exp2 on fma/alu pipes (no MUFU). Inputs <= 0.
__device__ __forceinline__ float fexp2(float x) {
    x = fmaxf(x, -126.0f);
    float r = rintf(x);
    float f = x - r;
    float p = 1.3333558e-3f;
    p = fmaf(p, f, 9.6181291e-3f);
    p = fmaf(p, f, 5.5504109e-2f);
    p = fmaf(p, f, 2.4022651e-1f);
    p = fmaf(p, f, 6.9314718e-1f);
    p = fmaf(p, f, 1.0f);
    return __int_as_float(__float_as_int(p) + (((int)r) << 23));
}

__device__ __forceinline__ void cp_async16(unsigned smem_dst, const float* gmem_src) {
    asm volatile("cp.async.cg.shared.global [%0], [%1], 16;\n"
                 :: "r"(smem_dst), "l"(gmem_src));
}

// ---------------------------------------------------------------------------
// Pre-round x and weights to tf32 once.
// ---------------------------------------------------------------------------
__global__ __launch_bounds__(256)
void pre_round_kernel(const float* __restrict__ x,
                      const float* __restrict__ Wq, const float* __restrict__ Wk,
                      const float* __restrict__ Wv, const float* __restrict__ Wo)
{
    int i4 = blockIdx.x * blockDim.x + threadIdx.x;
    const int tot4 = (NX + 4 * NW) / 4;
    if (i4 >= tot4) return;
    int i = i4 * 4;
    const float* src;
    float* dst;
    if (i < NX) { src = x + i; dst = g_xr + i; }
    else {
        int j = i - NX;
        int t = j / NW;
        int o = j - t * NW;
        src = (t == 0 ? Wq : t == 1 ? Wk : t == 2 ? Wv : Wo) + o;
        dst = g_Wr + j;
    }
    float4 v = *(const float4*)src;
    v.x = rtf32(v.x); v.y = rtf32(v.y); v.z = rtf32(v.z); v.w = rtf32(v.w);
    *(float4*)dst = v;
}

// ---------------------------------------------------------------------------
// TF32 wmma GEMM: C = A[M,K] @ W[N,K]^T + bias[N]
// 128 threads (4 warps), block 128x128, warp tile 64x64, 2-stage cp.async,
// 2 CTAs/SM (independent barriers -> latency hiding across CTAs).
// ---------------------------------------------------------------------------
#define GLDA 36
#define SLDA 20
#define AB_STG (128 * GLDA)                    // one stage of one array
#define GEMM_SMEM_FLOATS (4 * AB_STG)          // A[2] + B[2]
#define GEMM_SMEM_BYTES (GEMM_SMEM_FLOATS * 4)

template <bool QKV>
__global__ __launch_bounds__(128, 2)
void gemm_tf32(const float* __restrict__ A,
               const float* __restrict__ W0, const float* __restrict__ W1,
               const float* __restrict__ W2,
               const float* __restrict__ b0, const float* __restrict__ b1,
               const float* __restrict__ b2,
               float* __restrict__ C0, float* __restrict__ C1,
               float* __restrict__ C2)
{
    extern __shared__ float smg[];
    float* As = smg;                 // 2 stages x 128 x GLDA
    float* Bs = As + 2 * AB_STG;     // 2 stages x 128 x GLDA

    const float* W; const float* bias; float* C;
    if (QKV) {
        int z = blockIdx.z;
        W = (z == 0) ? W0 : (z == 1) ? W1 : W2;
        bias = (z == 0) ? b0 : (z == 1) ? b1 : b2;
        C = (z == 0) ? C0 : (z == 1) ? C1 : C2;
    } else { W = W0; bias = b0; C = C0; }

    const int tid = threadIdx.x;
    const int warpId = tid >> 5;
    const int lane = tid & 31;
    const int wm = warpId & 1;       // 64-row slab
    const int wn = warpId >> 1;      // 64-col slab
    const int blockRow = blockIdx.y * 128;
    const int blockCol = blockIdx.x * 128;

    const unsigned As_u = (unsigned)__cvta_generic_to_shared(As);
    const unsigned Bs_u = (unsigned)__cvta_generic_to_shared(Bs);

    wmma::fragment<wmma::accumulator, 16, 16, 8, float> acc[4][4];
#pragma unroll
    for (int i = 0; i < 4; ++i)
#pragma unroll
        for (int j = 0; j < 4; ++j) wmma::fill_fragment(acc[i][j], 0.0f);

    auto load_stage = [&](int s, int k0) {
#pragma unroll
        for (int l = 0; l < 8; ++l) {             // A: 1024 float4 / 128 thr
            int id = tid + l * 128;
            int row = id >> 3;
            int c4 = (id & 7) * 4;
            unsigned off = (unsigned)((s * AB_STG + row * GLDA + c4) * 4);
            cp_async16(As_u + off, A + (size_t)(blockRow + row) * D_MODEL + k0 + c4);
        }
#pragma unroll
        for (int l = 0; l < 8; ++l) {             // B: 1024 float4
            int id = tid + l * 128;
            int row = id >> 3;
            int c4 = (id & 7) * 4;
            unsigned off = (unsigned)((s * AB_STG + row * GLDA + c4) * 4);
            cp_async16(Bs_u + off, W + (size_t)(blockCol + row) * D_MODEL + k0 + c4);
        }
        asm volatile("cp.async.commit_group;\n" ::);
    };

    load_stage(0, 0);

    const int NT = D_MODEL / 32;
    for (int t = 0; t < NT; ++t) {
        if (t + 1 < NT) {
            load_stage((t + 1) & 1, (t + 1) * 32);
            asm volatile("cp.async.wait_group 1;\n" ::);
        } else {
            asm volatile("cp.async.wait_group 0;\n" ::);
        }
        __syncthreads();

        const float* Asb = As + (t & 1) * AB_STG;
        const float* Bsb = Bs + (t & 1) * AB_STG;
#pragma unroll
        for (int kk = 0; kk < 32; kk += 8) {
            wmma::fragment<wmma::matrix_a, 16, 16, 8, wmma::precision::tf32,
                           wmma::row_major> a[4];
            wmma::fragment<wmma::matrix_b, 16, 16, 8, wmma::precision::tf32,
                           wmma::col_major> b[4];
#pragma unroll
            for (int i = 0; i < 4; ++i)
                wmma::load_matrix_sync(a[i], Asb + (wm * 64 + i * 16) * GLDA + kk, GLDA);
#pragma unroll
            for (int j = 0; j < 4; ++j)
                wmma::load_matrix_sync(b[j], Bsb + (wn * 64 + j * 16) * GLDA + kk, GLDA);
#pragma unroll
            for (int i = 0; i < 4; ++i)
#pragma unroll
                for (int j = 0; j < 4; ++j)
                    wmma::mma_sync(acc[i][j], a[i], b[j], acc[i][j]);
        }
        __syncthreads();
    }

    // Epilogue: stage 16x16 tiles through smem (aliases As), add bias, scatter.
    float* stg = As + warpId * 16 * SLDA;
#pragma unroll
    for (int i = 0; i < 4; ++i) {
#pragma unroll
        for (int j = 0; j < 4; ++j) {
            wmma::store_matrix_sync(stg, acc[i][j], SLDA, wmma::mem_row_major);
            __syncwarp();
            int r = lane >> 1;
            int cb = (lane & 1) * 8;
            int m = blockRow + wm * 64 + i * 16 + r;
#pragma unroll
            for (int c = 0; c < 8; ++c) {
                int n = blockCol + wn * 64 + j * 16 + cb + c;
                float val = stg[r * SLDA + cb + c] + __ldg(&bias[n]);
                if (QKV) {
                    int b_ = m / SEQ;
                    int s_ = m - b_ * SEQ;
                    int h_ = n / DK;
                    int d_ = n - h_ * DK;
                    C[(((size_t)(b_ * N_HEADS + h_) * SEQ) + s_) * DK + d_] = rtf32(val);
                } else {
                    C[(size_t)m * D_MODEL + n] = val;
                }
            }
            __syncwarp();
        }
    }
}

// ---------------------------------------------------------------------------
// Causal flash attention, TF32 wmma. BQ=128 q-rows per CTA, kv tiles of 64.
// 256 threads = 8 warps as 4(m)x2(n), warp tile 32x32. cp.async double-buffered
// K/V, Q persistent in fragments, V row_major, poly-exp2 softmax 2 thr/row.
// ---------------------------------------------------------------------------
#define BQ 128
#define BKV 64
#define FLD 68
#define KV_STG (64 * FLD)
#define FLASH_SMEM_FLOATS (4 * KV_STG + 2 * (128 * FLD) + 256)
#define FLASH_SMEM_BYTES (FLASH_SMEM_FLOATS * 4)

__global__ __launch_bounds__(256, 1)
void flash_tf32()
{
    extern __shared__ float sm[];
    float* Ks  = sm;                      // 2 x [64][FLD]
    float* Vs  = Ks + 2 * KV_STG;         // 2 x [64][FLD]
    float* Ss  = Vs + 2 * KV_STG;         // [128][FLD] scores -> P
    float* QPV = Ss + 128 * FLD;          // [128][FLD] Q staging, then PV
    float* mrow = QPV + 128 * FLD;        // [128]
    float* lrow = mrow + 128;             // [128]

    const int bh = blockIdx.y;
    const int qt = blockIdx.x;
    const int b = bh / N_HEADS;
    const int h = bh - b * N_HEADS;

    const float* Qg = g_Q + (size_t)bh * SEQ * DK;
    const float* Kg = g_K + (size_t)bh * SEQ * DK;
    const float* Vg = g_V + (size_t)bh * SEQ * DK;

    const int tid = threadIdx.x;
    const int warpId = tid >> 5;
    const int wm = warpId & 3;            // rows wm*32..+31
    const int wn = warpId >> 2;           // cols wn*32..+31
    const int q0 = qt * BQ;

    const int row = tid >> 1;             // 0..127
    const int part = tid & 1;
    const int cbase = part * 32;
    const int qi = q0 + row;

    const unsigned Ks_u = (unsigned)__cvta_generic_to_shared(Ks);
    const unsigned Vs_u = (unsigned)__cvta_generic_to_shared(Vs);

    const float qscale = 0.125f * 1.44269504089f;  // scale * log2(e)

    auto prefetch_kv = [&](int kt) {
        int k0 = kt * BKV;
        unsigned sbase = (unsigned)((kt & 1) * KV_STG * 4);
#pragma unroll
        for (int l = 0; l < 4; ++l) {
            int id = tid + l * 256;
            int r = id >> 4;
            int c4 = (id & 15) * 4;
            unsigned off = sbase + (unsigned)((r * FLD + c4) * 4);
            cp_async16(Ks_u + off, Kg + (size_t)(k0 + r) * DK + c4);
            cp_async16(Vs_u + off, Vg + (size_t)(k0 + r) * DK + c4);
        }
        asm volatile("cp.async.commit_group;\n" ::);
    };
    prefetch_kv(0);

    // stage Q (scaled) into QPV, hoist into persistent fragments
#pragma unroll
    for (int l = 0; l < 8; ++l) {
        int id = tid + l * 256;
        int r = id >> 4;
        int c4 = (id & 15) * 4;
        float4 v = *(const float4*)(Qg + (size_t)(q0 + r) * DK + c4);
        v.x = rtf32(v.x * qscale); v.y = rtf32(v.y * qscale);
        v.z = rtf32(v.z * qscale); v.w = rtf32(v.w * qscale);
        *(float4*)(QPV + r * FLD + c4) = v;
    }
    if (tid < 128) { mrow[tid] = -1e30f; lrow[tid] = 0.f; }
    __syncthreads();

    wmma::fragment<wmma::matrix_a, 16, 16, 8, wmma::precision::tf32,
                   wmma::row_major> qf[2][8];
#pragma unroll
    for (int i = 0; i < 2; ++i)
#pragma unroll
        for (int kk = 0; kk < 8; ++kk)
            wmma::load_matrix_sync(qf[i][kk],
                                   QPV + (wm * 32 + i * 16) * FLD + kk * 8, FLD);

    float o[32];
#pragma unroll
    for (int c = 0; c < 32; ++c) o[c] = 0.f;

    const int NKT = 2 * qt + 2;           // kv tiles covering q0..q0+127
    for (int kt = 0; kt < NKT; ++kt) {
        if (kt + 1 < NKT) {
            prefetch_kv(kt + 1);
            asm volatile("cp.async.wait_group 1;\n" ::);
        } else {
            asm volatile("cp.async.wait_group 0;\n" ::);
        }
        __syncthreads();                          // B1: KV[kt] visible

        const float* Kb = Ks + (kt & 1) * KV_STG;
        const float* Vb = Vs + (kt & 1) * KV_STG;
        const int k0 = kt * BKV;

        // S = Q @ K^T  (warp 32 rows x 32 cols)
        {
            wmma::fragment<wmma::accumulator, 16, 16, 8, float> s[2][2];
#pragma unroll
            for (int i = 0; i < 2; ++i)
#pragma unroll
                for (int j = 0; j < 2; ++j) wmma::fill_fragment(s[i][j], 0.0f);
#pragma unroll
            for (int kk = 0; kk < 8; ++kk) {
                wmma::fragment<wmma::matrix_b, 16, 16, 8, wmma::precision::tf32,
                               wmma::col_major> b0, b1;
                wmma::load_matrix_sync(b0, Kb + (wn * 32) * FLD + kk * 8, FLD);
                wmma::load_matrix_sync(b1, Kb + (wn * 32 + 16) * FLD + kk * 8, FLD);
#pragma unroll
                for (int i = 0; i < 2; ++i) {
                    wmma::mma_sync(s[i][0], qf[i][kk], b0, s[i][0]);
                    wmma::mma_sync(s[i][1], qf[i][kk], b1, s[i][1]);
                }
            }
#pragma unroll
            for (int i = 0; i < 2; ++i)
#pragma unroll
                for (int j = 0; j < 2; ++j)
                    wmma::store_matrix_sync(
                        Ss + (wm * 32 + i * 16) * FLD + wn * 32 + j * 16,
                        s[i][j], FLD, wmma::mem_row_major);
        }
        __syncthreads();                          // B2: Ss ready

        // online softmax (base-2), 2 threads per row
        float corr;
        {
            float vals[32];
            float mloc = -1e30f;
#pragma unroll
            for (int c = 0; c < 32; ++c) {
                int kj = k0 + cbase + c;
                float v = (kj <= qi) ? Ss[row * FLD + cbase + c] : -1e30f;
                vals[c] = v;
                mloc = fmaxf(mloc, v);
            }
            mloc = fmaxf(mloc, __shfl_xor_sync(0xFFFFFFFF, mloc, 1));
            float mold = mrow[row];
            float lold = lrow[row];
            __syncwarp();
            float mnew = fmaxf(mold, mloc);
            float suml = 0.f;
#pragma unroll
            for (int c = 0; c < 32; ++c) {
                float p = fexp2(vals[c] - mnew);
                Ss[row * FLD + cbase + c] = rtf32(p);
                suml += p;
            }
            suml += __shfl_xor_sync(0xFFFFFFFF, suml, 1);
            corr = fexp2(mold - mnew);
            if (part == 0) {
                mrow[row] = mnew;
                lrow[row] = lold * corr + suml;
            }
        }
        __syncthreads();                          // B3: P ready

        // PV = P @ V  (V row_major over kv)
        {
            wmma::fragment<wmma::accumulator, 16, 16, 8, float> p[2][2];
#pragma unroll
            for (int i = 0; i < 2; ++i)
#pragma unroll
                for (int j = 0; j < 2; ++j) wmma::fill_fragment(p[i][j], 0.0f);
#pragma unroll
            for (int kk = 0; kk < 8; ++kk) {
                wmma::fragment<wmma::matrix_a, 16, 16, 8, wmma::precision::tf32,
                               wmma::row_major> a0, a1;
                wmma::fragment<wmma::matrix_b, 16, 16, 8, wmma::precision::tf32,
                               wmma::row_major> b0, b1;
                wmma::load_matrix_sync(a0, Ss + (wm * 32) * FLD + kk * 8, FLD);
                wmma::load_matrix_sync(a1, Ss + (wm * 32 + 16) * FLD + kk * 8, FLD);
                wmma::load_matrix_sync(b0, Vb + (kk * 8) * FLD + wn * 32, FLD);
                wmma::load_matrix_sync(b1, Vb + (kk * 8) * FLD + wn * 32 + 16, FLD);
                wmma::mma_sync(p[0][0], a0, b0, p[0][0]);
                wmma::mma_sync(p[0][1], a0, b1, p[0][1]);
                wmma::mma_sync(p[1][0], a1, b0, p[1][0]);
                wmma::mma_sync(p[1][1], a1, b1, p[1][1]);
            }
#pragma unroll
            for (int i = 0; i < 2; ++i)
#pragma unroll
                for (int j = 0; j < 2; ++j)
                    wmma::store_matrix_sync(
                        QPV + (wm * 32 + i * 16) * FLD + wn * 32 + j * 16,
                        p[i][j], FLD, wmma::mem_row_major);
        }
        __syncthreads();                          // B4: PV ready

#pragma unroll
        for (int c = 0; c < 32; ++c)
            o[c] = o[c] * corr + QPV[row * FLD + cbase + c];
    }

    float linv = 1.f / lrow[row];
#pragma unroll
    for (int c = 0; c < 32; ++c) {
        g_ctx[((size_t)b * SEQ + q0 + row) * D_MODEL + h * DK + cbase + c] =
            rtf32(o[c] * linv);
    }
}

// ---------------------------------------------------------------------------
extern "C" void kernel_launch(void* const* d_in, const int* in_sizes, int n_in,
                              void* d_out, int out_size)
{
    const float* x  = (const float*)d_in[0];
    const float* Wq = (const float*)d_in[1];
    const float* bq = (const float*)d_in[2];
    const float* Wk = (const float*)d_in[3];
    const float* bk = (const float*)d_in[4];
    const float* Wv = (const float*)d_in[5];
    const float* bv = (const float*)d_in[6];
    const float* Wo = (const float*)d_in[7];
    const float* bo = (const float*)d_in[8];
    float* out = (float*)d_out;

    float *pQ, *pK, *pV, *pCtx, *pXr, *pWr;
    cudaGetSymbolAddress((void**)&pQ, g_Q);
    cudaGetSymbolAddress((void**)&pK, g_K);
    cudaGetSymbolAddress((void**)&pV, g_V);
    cudaGetSymbolAddress((void**)&pCtx, g_ctx);
    cudaGetSymbolAddress((void**)&pXr, g_xr);
    cudaGetSymbolAddress((void**)&pWr, g_Wr);

    cudaFuncSetAttribute(flash_tf32,
                         cudaFuncAttributeMaxDynamicSharedMemorySize,
                         FLASH_SMEM_BYTES);
    cudaFuncSetAttribute(gemm_tf32<true>,
                         cudaFuncAttributeMaxDynamicSharedMemorySize,
                         GEMM_SMEM_BYTES);
    cudaFuncSetAttribute(gemm_tf32<false>,
                         cudaFuncAttributeMaxDynamicSharedMemorySize,
                         GEMM_SMEM_BYTES);

    {
        int tot4 = (NX + 4 * NW) / 4;
        pre_round_kernel<<<(tot4 + 255) / 256, 256>>>(x, Wq, Wk, Wv, Wo);
    }

    dim3 qkvGrid(D_MODEL / 128, M_TOT / 128, 3);   // (8, 32, 3)
    gemm_tf32<true><<<qkvGrid, 128, GEMM_SMEM_BYTES>>>(
        pXr, pWr, pWr + NW, pWr + 2 * NW, bq, bk, bv, pQ, pK, pV);

    dim3 flashGrid(SEQ / BQ, BATCH * N_HEADS);     // (16, 32)
    flash_tf32<<<flashGrid, 256, FLASH_SMEM_BYTES>>>();

    dim3 gemmGrid(D_MODEL / 128, M_TOT / 128, 1);  // (8, 32)
    gemm_tf32<false><<<gemmGrid, 128, GEMM_SMEM_BYTES>>>(
        pCtx, pWr + 3 * NW, nullptr, nullptr, bo, nullptr, nullptr,
        out, nullptr, nullptr);
}

// round 12
// speedup vs baseline: 1.0894x; 1.0894x over previous
#include <cuda_runtime.h>
#include <cstdint>
#include <mma.h>
#include <math.h>

using namespace nvcuda;

#define D_MODEL 1024
#define N_HEADS 16
#define DK 64
#define BATCH 2
#define SEQ 2048
#define M_TOT (BATCH * SEQ)   // 4096
#define NX (M_TOT * D_MODEL)
#define NW (D_MODEL * D_MODEL)

__device__ float g_Q[BATCH * N_HEADS * SEQ * DK];   // [B,H,S,dk] tf32-rounded
__device__ float g_K[BATCH * N_HEADS * SEQ * DK];
__device__ float g_V[BATCH * N_HEADS * SEQ * DK];
__device__ float g_ctx[BATCH * SEQ * D_MODEL];      // [B,S,D]
__device__ float g_xr[NX];                          // tf32-rounded x
__device__ float g_Wr[4 * NW];                      // tf32-rounded Wq,Wk,Wv,Wo

__device__ __forceinline__ float rtf32(float a) {
    float r;
    asm("cvt.rna.tf32.f32 %0, %1;" : "=f"(r) : "f"(a));
    return r;
}

// fast exp2 on fma/alu pipes (no MUFU). Inputs <= 0.
__device__ __forceinline__ float fexp2(float x) {
    x = fmaxf(x, -126.0f);
    float r = rintf(x);
    float f = x - r;
    float p = 1.3333558e-3f;
    p = fmaf(p, f, 9.6181291e-3f);
    p = fmaf(p, f, 5.5504109e-2f);
    p = fmaf(p, f, 2.4022651e-1f);
    p = fmaf(p, f, 6.9314718e-1f);
    p = fmaf(p, f, 1.0f);
    return __int_as_float(__float_as_int(p) + (((int)r) << 23));
}

__device__ __forceinline__ void cp_async16(unsigned smem_dst, const float* gmem_src) {
    asm volatile("cp.async.cg.shared.global [%0], [%1], 16;\n"
                 :: "r"(smem_dst), "l"(gmem_src));
}

// ---------------------------------------------------------------------------
// Pre-round x and weights to tf32 once.
// ---------------------------------------------------------------------------
__global__ __launch_bounds__(256)
void pre_round_kernel(const float* __restrict__ x,
                      const float* __restrict__ Wq, const float* __restrict__ Wk,
                      const float* __restrict__ Wv, const float* __restrict__ Wo)
{
    int i4 = blockIdx.x * blockDim.x + threadIdx.x;
    const int tot4 = (NX + 4 * NW) / 4;
    if (i4 >= tot4) return;
    int i = i4 * 4;
    const float* src;
    float* dst;
    if (i < NX) { src = x + i; dst = g_xr + i; }
    else {
        int j = i - NX;
        int t = j / NW;
        int o = j - t * NW;
        src = (t == 0 ? Wq : t == 1 ? Wk : t == 2 ? Wv : Wo) + o;
        dst = g_Wr + j;
    }
    float4 v = *(const float4*)src;
    v.x = rtf32(v.x); v.y = rtf32(v.y); v.z = rtf32(v.z); v.w = rtf32(v.w);
    *(float4*)dst = v;
}

// ---------------------------------------------------------------------------
// TF32 wmma GEMM, cp.async 3-stage, 1 barrier/iter (R7 config, best known):
// C = A[M,K] @ W[N,K]^T + bias[N]. Block 128x256, BK=32, 8 warps, 64x64 tiles.
// ---------------------------------------------------------------------------
#define GLDA 36
#define SLDA 20
#define A_STG (128 * GLDA)
#define B_STG (256 * GLDA)
#define GEMM_SMEM_FLOATS (3 * A_STG + 3 * B_STG)
#define GEMM_SMEM_BYTES (GEMM_SMEM_FLOATS * 4)

template <bool QKV>
__global__ __launch_bounds__(256)
void gemm_tf32(const float* __restrict__ A,
               const float* __restrict__ W0, const float* __restrict__ W1,
               const float* __restrict__ W2,
               const float* __restrict__ b0, const float* __restrict__ b1,
               const float* __restrict__ b2,
               float* __restrict__ C0, float* __restrict__ C1,
               float* __restrict__ C2)
{
    extern __shared__ float smg[];
    float* As = smg;
    float* Bs = As + 3 * A_STG;

    const float* W; const float* bias; float* C;
    if (QKV) {
        int z = blockIdx.z;
        W = (z == 0) ? W0 : (z == 1) ? W1 : W2;
        bias = (z == 0) ? b0 : (z == 1) ? b1 : b2;
        C = (z == 0) ? C0 : (z == 1) ? C1 : C2;
    } else { W = W0; bias = b0; C = C0; }

    const int tid = threadIdx.x;
    const int warpId = tid >> 5;
    const int lane = tid & 31;
    const int wm = warpId & 1;
    const int wn = warpId >> 1;
    const int blockRow = blockIdx.y * 128;
    const int blockCol = blockIdx.x * 256;

    const unsigned As_u = (unsigned)__cvta_generic_to_shared(As);
    const unsigned Bs_u = (unsigned)__cvta_generic_to_shared(Bs);

    wmma::fragment<wmma::accumulator, 16, 16, 8, float> acc[4][4];
#pragma unroll
    for (int i = 0; i < 4; ++i)
#pragma unroll
        for (int j = 0; j < 4; ++j) wmma::fill_fragment(acc[i][j], 0.0f);

    auto load_stage = [&](int s, int k0) {
#pragma unroll
        for (int l = 0; l < 4; ++l) {
            int id = tid + l * 256;
            int row = id >> 3;
            int c4 = (id & 7) * 4;
            unsigned off = (unsigned)((s * A_STG + row * GLDA + c4) * 4);
            cp_async16(As_u + off, A + (size_t)(blockRow + row) * D_MODEL + k0 + c4);
        }
#pragma unroll
        for (int l = 0; l < 8; ++l) {
            int id = tid + l * 256;
            int row = id >> 3;
            int c4 = (id & 7) * 4;
            unsigned off = (unsigned)((s * B_STG + row * GLDA + c4) * 4);
            cp_async16(Bs_u + off, W + (size_t)(blockCol + row) * D_MODEL + k0 + c4);
        }
        asm volatile("cp.async.commit_group;\n" ::);
    };

    load_stage(0, 0);
    load_stage(1, 32);

    const int NT = D_MODEL / 32;
    for (int t = 0; t < NT; ++t) {
        if (t + 1 < NT) {
            asm volatile("cp.async.wait_group 1;\n" ::);
        } else {
            asm volatile("cp.async.wait_group 0;\n" ::);
        }
        __syncthreads();

        if (t + 2 < NT)
            load_stage((t + 2) % 3, (t + 2) * 32);

        const float* Asb = As + (t % 3) * A_STG;
        const float* Bsb = Bs + (t % 3) * B_STG;
#pragma unroll
        for (int kk = 0; kk < 32; kk += 8) {
            wmma::fragment<wmma::matrix_a, 16, 16, 8, wmma::precision::tf32,
                           wmma::row_major> a[4];
            wmma::fragment<wmma::matrix_b, 16, 16, 8, wmma::precision::tf32,
                           wmma::col_major> b[4];
#pragma unroll
            for (int i = 0; i < 4; ++i)
                wmma::load_matrix_sync(a[i], Asb + (wm * 64 + i * 16) * GLDA + kk, GLDA);
#pragma unroll
            for (int j = 0; j < 4; ++j)
                wmma::load_matrix_sync(b[j], Bsb + (wn * 64 + j * 16) * GLDA + kk, GLDA);
#pragma unroll
            for (int i = 0; i < 4; ++i)
#pragma unroll
                for (int j = 0; j < 4; ++j)
                    wmma::mma_sync(acc[i][j], a[i], b[j], acc[i][j]);
        }
    }
    __syncthreads();

    float* stg = As + warpId * 16 * SLDA;
#pragma unroll
    for (int i = 0; i < 4; ++i) {
#pragma unroll
        for (int j = 0; j < 4; ++j) {
            wmma::store_matrix_sync(stg, acc[i][j], SLDA, wmma::mem_row_major);
            __syncwarp();
            int r = lane >> 1;
            int cb = (lane & 1) * 8;
            int m = blockRow + wm * 64 + i * 16 + r;
#pragma unroll
            for (int c = 0; c < 8; ++c) {
                int n = blockCol + wn * 64 + j * 16 + cb + c;
                float val = stg[r * SLDA + cb + c] + __ldg(&bias[n]);
                if (QKV) {
                    int b_ = m / SEQ;
                    int s_ = m - b_ * SEQ;
                    int h_ = n / DK;
                    int d_ = n - h_ * DK;
                    C[(((size_t)(b_ * N_HEADS + h_) * SEQ) + s_) * DK + d_] = rtf32(val);
                } else {
                    C[(size_t)m * D_MODEL + n] = val;
                }
            }
            __syncwarp();
        }
    }
}

// ---------------------------------------------------------------------------
// Causal flash attention (R7 config + balance/mask/cvt fixes).
// 128 threads = 4 warps, warp tile 32x32, 2 CTAs/SM, BQ=BKV=64.
// qt reversed for LPT scheduling; masking only on the diagonal tile;
// no rtf32 on P or scaled Q (HMMA truncates operands anyway).
// ---------------------------------------------------------------------------
#define BQ 64
#define BKV 64
#define FLD 68
#define KV_STG (64 * FLD)
#define FLASH_SMEM_FLOATS (4 * KV_STG + 2 * KV_STG + 128)
#define FLASH_SMEM_BYTES (FLASH_SMEM_FLOATS * 4)

__global__ __launch_bounds__(128, 2)
void flash_tf32()
{
    extern __shared__ float sm[];
    float* Ks  = sm;                      // 2 x [64][FLD]
    float* Vs  = Ks + 2 * KV_STG;         // 2 x [64][FLD]
    float* Ss  = Vs + 2 * KV_STG;         // [64][FLD] scores -> P
    float* QPV = Ss + KV_STG;             // Q staging, then PV tile
    float* mrow = QPV + KV_STG;           // [64]
    float* lrow = mrow + 64;              // [64]

    const int bh = blockIdx.y;
    const int qt = gridDim.x - 1 - blockIdx.x;   // LPT: heaviest CTAs first
    const int b = bh / N_HEADS;
    const int h = bh - b * N_HEADS;

    const float* Qg = g_Q + (size_t)bh * SEQ * DK;
    const float* Kg = g_K + (size_t)bh * SEQ * DK;
    const float* Vg = g_V + (size_t)bh * SEQ * DK;

    const int tid = threadIdx.x;
    const int warpId = tid >> 5;
    const int wm = warpId & 1;            // rows wm*32..+31
    const int wn = warpId >> 1;           // cols wn*32..+31
    const int q0 = qt * BQ;

    const int row = tid >> 1;             // 0..63
    const int part = tid & 1;
    const int cbase = part * 32;
    const int qi = q0 + row;

    const unsigned Ks_u = (unsigned)__cvta_generic_to_shared(Ks);
    const unsigned Vs_u = (unsigned)__cvta_generic_to_shared(Vs);

    const float qscale = 0.125f * 1.44269504089f;  // scale * log2(e)

    auto prefetch_kv = [&](int kt) {
        int k0 = kt * BKV;
        unsigned sbase = (unsigned)((kt & 1) * KV_STG * 4);
#pragma unroll
        for (int l = 0; l < 8; ++l) {
            int id = tid + l * 128;
            int r = id >> 4;
            int c4 = (id & 15) * 4;
            unsigned off = sbase + (unsigned)((r * FLD + c4) * 4);
            cp_async16(Ks_u + off, Kg + (size_t)(k0 + r) * DK + c4);
            cp_async16(Vs_u + off, Vg + (size_t)(k0 + r) * DK + c4);
        }
        asm volatile("cp.async.commit_group;\n" ::);
    };
    prefetch_kv(0);

    // stage Q (scaled) into QPV, hoist into persistent fragments
#pragma unroll
    for (int l = 0; l < 8; ++l) {
        int id = tid + l * 128;
        int r = id >> 4;
        int c4 = (id & 15) * 4;
        float4 v = *(const float4*)(Qg + (size_t)(q0 + r) * DK + c4);
        v.x *= qscale; v.y *= qscale; v.z *= qscale; v.w *= qscale;
        *(float4*)(QPV + r * FLD + c4) = v;
    }
    if (tid < 64) { mrow[tid] = -1e30f; lrow[tid] = 0.f; }
    __syncthreads();

    wmma::fragment<wmma::matrix_a, 16, 16, 8, wmma::precision::tf32,
                   wmma::row_major> qf[2][8];
#pragma unroll
    for (int i = 0; i < 2; ++i)
#pragma unroll
        for (int kk = 0; kk < 8; ++kk)
            wmma::load_matrix_sync(qf[i][kk],
                                   QPV + (wm * 32 + i * 16) * FLD + kk * 8, FLD);

    float o[32];
#pragma unroll
    for (int c = 0; c < 32; ++c) o[c] = 0.f;

    for (int kt = 0; kt <= qt; ++kt) {
        if (kt + 1 <= qt) {
            prefetch_kv(kt + 1);
            asm volatile("cp.async.wait_group 1;\n" ::);
        } else {
            asm volatile("cp.async.wait_group 0;\n" ::);
        }
        __syncthreads();                          // B1: KV[kt] visible

        const float* Kb = Ks + (kt & 1) * KV_STG;
        const float* Vb = Vs + (kt & 1) * KV_STG;
        const int k0 = kt * BKV;
        const bool diag = (kt == qt);

        // S = Q @ K^T  (warp 32x32)
        {
            wmma::fragment<wmma::accumulator, 16, 16, 8, float> s[2][2];
#pragma unroll
            for (int i = 0; i < 2; ++i)
#pragma unroll
                for (int j = 0; j < 2; ++j) wmma::fill_fragment(s[i][j], 0.0f);
#pragma unroll
            for (int kk = 0; kk < 8; ++kk) {
                wmma::fragment<wmma::matrix_b, 16, 16, 8, wmma::precision::tf32,
                               wmma::col_major> b0, b1;
                wmma::load_matrix_sync(b0, Kb + (wn * 32) * FLD + kk * 8, FLD);
                wmma::load_matrix_sync(b1, Kb + (wn * 32 + 16) * FLD + kk * 8, FLD);
#pragma unroll
                for (int i = 0; i < 2; ++i) {
                    wmma::mma_sync(s[i][0], qf[i][kk], b0, s[i][0]);
                    wmma::mma_sync(s[i][1], qf[i][kk], b1, s[i][1]);
                }
            }
#pragma unroll
            for (int i = 0; i < 2; ++i)
#pragma unroll
                for (int j = 0; j < 2; ++j)
                    wmma::store_matrix_sync(
                        Ss + (wm * 32 + i * 16) * FLD + wn * 32 + j * 16,
                        s[i][j], FLD, wmma::mem_row_major);
        }
        __syncthreads();                          // B2: Ss ready

        // online softmax (base-2), 2 threads per row
        float corr;
        {
            float vals[32];
            float mloc = -1e30f;
            if (diag) {
#pragma unroll
                for (int c = 0; c < 32; ++c) {
                    int kj = k0 + cbase + c;
                    float v = (kj <= qi) ? Ss[row * FLD + cbase + c] : -1e30f;
                    vals[c] = v;
                    mloc = fmaxf(mloc, v);
                }
            } else {
#pragma unroll
                for (int c = 0; c < 32; ++c) {
                    float v = Ss[row * FLD + cbase + c];
                    vals[c] = v;
                    mloc = fmaxf(mloc, v);
                }
            }
            mloc = fmaxf(mloc, __shfl_xor_sync(0xFFFFFFFF, mloc, 1));
            float mold = mrow[row];
            float lold = lrow[row];
            __syncwarp();
            float mnew = fmaxf(mold, mloc);
            float suml = 0.f;
#pragma unroll
            for (int c = 0; c < 32; ++c) {
                float p = fexp2(vals[c] - mnew);
                Ss[row * FLD + cbase + c] = p;     // HMMA truncates to tf32
                suml += p;
            }
            suml += __shfl_xor_sync(0xFFFFFFFF, suml, 1);
            corr = fexp2(mold - mnew);
            if (part == 0) {
                mrow[row] = mnew;
                lrow[row] = lold * corr + suml;
            }
        }
        __syncthreads();                          // B3: P ready

        // PV = P @ V  (V row_major over kv)
        {
            wmma::fragment<wmma::accumulator, 16, 16, 8, float> p[2][2];
#pragma unroll
            for (int i = 0; i < 2; ++i)
#pragma unroll
                for (int j = 0; j < 2; ++j) wmma::fill_fragment(p[i][j], 0.0f);
#pragma unroll
            for (int kk = 0; kk < 8; ++kk) {
                wmma::fragment<wmma::matrix_a, 16, 16, 8, wmma::precision::tf32,
                               wmma::row_major> a0, a1;
                wmma::fragment<wmma::matrix_b, 16, 16, 8, wmma::precision::tf32,
                               wmma::row_major> b0, b1;
                wmma::load_matrix_sync(a0, Ss + (wm * 32) * FLD + kk * 8, FLD);
                wmma::load_matrix_sync(a1, Ss + (wm * 32 + 16) * FLD + kk * 8, FLD);
                wmma::load_matrix_sync(b0, Vb + (kk * 8) * FLD + wn * 32, FLD);
                wmma::load_matrix_sync(b1, Vb + (kk * 8) * FLD + wn * 32 + 16, FLD);
                wmma::mma_sync(p[0][0], a0, b0, p[0][0]);
                wmma::mma_sync(p[0][1], a0, b1, p[0][1]);
                wmma::mma_sync(p[1][0], a1, b0, p[1][0]);
                wmma::mma_sync(p[1][1], a1, b1, p[1][1]);
            }
#pragma unroll
            for (int i = 0; i < 2; ++i)
#pragma unroll
                for (int j = 0; j < 2; ++j)
                    wmma::store_matrix_sync(
                        QPV + (wm * 32 + i * 16) * FLD + wn * 32 + j * 16,
                        p[i][j], FLD, wmma::mem_row_major);
        }
        __syncthreads();                          // B4: PV ready

#pragma unroll
        for (int c = 0; c < 32; ++c)
            o[c] = o[c] * corr + QPV[row * FLD + cbase + c];
    }

    float linv = 1.f / lrow[row];
#pragma unroll
    for (int c = 0; c < 32; ++c) {
        g_ctx[((size_t)b * SEQ + q0 + row) * D_MODEL + h * DK + cbase + c] =
            o[c] * linv;
    }
}

// ---------------------------------------------------------------------------
extern "C" void kernel_launch(void* const* d_in, const int* in_sizes, int n_in,
                              void* d_out, int out_size)
{
    const float* x  = (const float*)d_in[0];
    const float* Wq = (const float*)d_in[1];
    const float* bq = (const float*)d_in[2];
    const float* Wk = (const float*)d_in[3];
    const float* bk = (const float*)d_in[4];
    const float* Wv = (const float*)d_in[5];
    const float* bv = (const float*)d_in[6];
    const float* Wo = (const float*)d_in[7];
    const float* bo = (const float*)d_in[8];
    float* out = (float*)d_out;

    float *pQ, *pK, *pV, *pCtx, *pXr, *pWr;
    cudaGetSymbolAddress((void**)&pQ, g_Q);
    cudaGetSymbolAddress((void**)&pK, g_K);
    cudaGetSymbolAddress((void**)&pV, g_V);
    cudaGetSymbolAddress((void**)&pCtx, g_ctx);
    cudaGetSymbolAddress((void**)&pXr, g_xr);
    cudaGetSymbolAddress((void**)&pWr, g_Wr);

    cudaFuncSetAttribute(flash_tf32,
                         cudaFuncAttributeMaxDynamicSharedMemorySize,
                         FLASH_SMEM_BYTES);
    cudaFuncSetAttribute(gemm_tf32<true>,
                         cudaFuncAttributeMaxDynamicSharedMemorySize,
                         GEMM_SMEM_BYTES);
    cudaFuncSetAttribute(gemm_tf32<false>,
                         cudaFuncAttributeMaxDynamicSharedMemorySize,
                         GEMM_SMEM_BYTES);

    {
        int tot4 = (NX + 4 * NW) / 4;
        pre_round_kernel<<<(tot4 + 255) / 256, 256>>>(x, Wq, Wk, Wv, Wo);
    }

    dim3 qkvGrid(D_MODEL / 256, M_TOT / 128, 3);   // (4, 32, 3)
    gemm_tf32<true><<<qkvGrid, 256, GEMM_SMEM_BYTES>>>(
        pXr, pWr, pWr + NW, pWr + 2 * NW, bq, bk, bv, pQ, pK, pV);

    dim3 flashGrid(SEQ / BQ, BATCH * N_HEADS);     // (32, 32)
    flash_tf32<<<flashGrid, 128, FLASH_SMEM_BYTES>>>();

    dim3 gemmGrid(D_MODEL / 256, M_TOT / 128, 1);  // (4, 32)
    gemm_tf32<false><<<gemmGrid, 256, GEMM_SMEM_BYTES>>>(
        pCtx, pWr + 3 * NW, nullptr, nullptr, bo, nullptr, nullptr,
        out, nullptr, nullptr);
}